// round 16
// baseline (speedup 1.0000x reference)
#include <cuda_runtime.h>

#define N 8192
#define THREADS 256
#define ROWS_PER_CTA 4
#define COL_HALF 4096
#define NUM_BLOCKS ((N / ROWS_PER_CTA) * 2)        // 4096: 4 rows x half width
#define COLS_PER_THREAD 4
#define ITERS (COL_HALF / (THREADS * COLS_PER_THREAD))   // 4
#define CONV_CTAS 256
#define CONV_PER_CTA (N / CONV_CTAS)               // 32 entries per converter CTA

typedef unsigned long long ull;
union f2u { float2 f; ull u; };

__device__ float        g_xs[N];
__device__ float        g_ys[N];
__device__ float        g_partials[NUM_BLOCKS];
__device__ unsigned int g_flag  = 0;
__device__ unsigned int g_count = 0;

__device__ __forceinline__ ull f2add(ull a, ull b) {
    ull c; asm("add.rn.f32x2 %0, %1, %2;" : "=l"(c) : "l"(a), "l"(b)); return c;
}
__device__ __forceinline__ ull f2mul(ull a, ull b) {
    ull c; asm("mul.rn.f32x2 %0, %1, %2;" : "=l"(c) : "l"(a), "l"(b)); return c;
}
__device__ __forceinline__ ull f2fma(ull a, ull b, ull c) {
    ull d; asm("fma.rn.f32x2 %0, %1, %2, %3;" : "=l"(d) : "l"(a), "l"(b), "l"(c)); return d;
}
__device__ __forceinline__ float fsqrt_a(float x) {
    float r; asm("sqrt.approx.f32 %0, %1;" : "=f"(r) : "f"(x)); return r;
}
__device__ __forceinline__ float frcp_a(float x) {
    float r; asm("rcp.approx.f32 %0, %1;" : "=f"(r) : "f"(x)); return r;
}

__global__ __launch_bounds__(THREADS, 5)
void stress_kernel(const float2* __restrict__ pos2,
                   const float*  __restrict__ dist,
                   float* __restrict__ out) {
    const int tid  = threadIdx.x;
    const int row0 = ((int)blockIdx.x >> 1) * ROWS_PER_CTA;
    const int col0 = ((int)blockIdx.x & 1) * COL_HALF;

    // ---- inline SoA conversion by the first CONV_CTAS CTAs ----
    if (blockIdx.x < CONV_CTAS) {
        if (tid < CONV_PER_CTA) {
            const int i = (int)blockIdx.x * CONV_PER_CTA + tid;
            float2 p = pos2[i];
            g_xs[i] = p.x;
            g_ys[i] = p.y;
            __threadfence();
        }
        __syncthreads();
        if (tid == 0)
            asm volatile("red.release.gpu.global.add.u32 [%0], %1;"
                         :: "l"(&g_flag), "r"(1u) : "memory");
    }

    // row positions (independent of SoA) while the gate settles
    f2u nx[ROWS_PER_CTA], ny[ROWS_PER_CTA];
    #pragma unroll
    for (int k = 0; k < ROWS_PER_CTA; k++) {
        float2 p = __ldg(&pos2[row0 + k]);
        nx[k].f.x = -p.x; nx[k].f.y = -p.x;
        ny[k].f.x = -p.y; ny[k].f.y = -p.y;
    }

    // ---- gate: wait until all converter CTAs have published ----
    if (tid == 0) {
        unsigned f;
        for (;;) {
            asm volatile("ld.acquire.gpu.global.u32 %0, [%1];"
                         : "=r"(f) : "l"(&g_flag) : "memory");
            if (f >= CONV_CTAS) break;
            __nanosleep(64);
        }
    }
    __syncthreads();

    const float* dr0 = dist + (size_t)row0 * N + col0;
    const float* dr1 = dr0 + N;
    const float* dr2 = dr1 + N;
    const float* dr3 = dr2 + N;

    f2u acc01, acc23;
    acc01.f.x = 0.f; acc01.f.y = 0.f;
    acc23.f.x = 0.f; acc23.f.y = 0.f;
    float acc_s = 0.f;

    f2u NEG1; NEG1.f.x = -1.f; NEG1.f.y = -1.f;

    for (int it = 0; it < ITERS; it++) {
        const int c = (it * THREADS + tid) * COLS_PER_THREAD;
        const int j = col0 + c;

        float4 x4 = __ldg(reinterpret_cast<const float4*>(&g_xs[j]));
        float4 y4 = __ldg(reinterpret_cast<const float4*>(&g_ys[j]));

        float4 d0 = __ldcs(reinterpret_cast<const float4*>(dr0 + c));
        float4 d1 = __ldcs(reinterpret_cast<const float4*>(dr1 + c));
        float4 d2 = __ldcs(reinterpret_cast<const float4*>(dr2 + c));
        float4 d3 = __ldcs(reinterpret_cast<const float4*>(dr3 + c));

        float m0 = fminf(fminf(d0.x, d0.y), fminf(d0.z, d0.w));
        float m1 = fminf(fminf(d1.x, d1.y), fminf(d1.z, d1.w));
        float m2 = fminf(fminf(d2.x, d2.y), fminf(d2.z, d2.w));
        float m3 = fminf(fminf(d3.x, d3.y), fminf(d3.z, d3.w));
        float mn = fminf(fminf(m0, m1), fminf(m2, m3));

        if (mn > 0.0f) {
            // SoA packs: register-pair halves of x4/y4, zero MOVs
            f2u xa, xb, ya, yb;
            xa.f.x = x4.x; xa.f.y = x4.y;  xb.f.x = x4.z; xb.f.y = x4.w;
            ya.f.x = y4.x; ya.f.y = y4.y;  yb.f.x = y4.z; yb.f.y = y4.w;

            auto grp = [&](const float4& d, ull nxp, ull nyp) {
                // Montgomery batched reciprocal: 1 MUFU.RCP / 4 elems
                float q01   = d.x * d.y;
                float q012  = q01 * d.z;
                float q0123 = q012 * d.w;
                float R  = frcp_a(q0123);
                float i3 = q012 * R;  float R3 = R  * d.w;
                float i2 = q01  * R3; float R2 = R3 * d.z;
                float i1 = d.x  * R2; float i0 = d.y * R2;
                f2u iv01; iv01.f.x = i0; iv01.f.y = i1;
                f2u iv23; iv23.f.x = i2; iv23.f.y = i3;

                ull dxa = f2add(xa.u, nxp);
                ull dya = f2add(ya.u, nyp);
                ull sqa = f2fma(dya, dya, f2mul(dxa, dxa));
                f2u sa; sa.u = sqa;
                f2u pa; pa.f.x = fsqrt_a(sa.f.x); pa.f.y = fsqrt_a(sa.f.y);
                ull qa = f2fma(pa.u, iv01.u, NEG1.u);     // pred/d - 1
                acc01.u = f2fma(qa, qa, acc01.u);

                ull dxb = f2add(xb.u, nxp);
                ull dyb = f2add(yb.u, nyp);
                ull sqb = f2fma(dyb, dyb, f2mul(dxb, dxb));
                f2u sb; sb.u = sqb;
                f2u pb; pb.f.x = fsqrt_a(sb.f.x); pb.f.y = fsqrt_a(sb.f.y);
                ull qb = f2fma(pb.u, iv23.u, NEG1.u);
                acc23.u = f2fma(qb, qb, acc23.u);
            };

            grp(d0, nx[0].u, ny[0].u);
            grp(d1, nx[1].u, ny[1].u);
            grp(d2, nx[2].u, ny[2].u);
            grp(d3, nx[3].u, ny[3].u);
        } else {
            // exact scalar fallback (rare: group contains a zero distance)
            auto safe = [&](float d, float xj, float yj, float px, float py) {
                float dx = xj + px, dy = yj + py;
                float sq = fmaf(dy, dy, dx * dx);
                float pr = fsqrt_a(sq);
                float q  = (pr - d) * frcp_a(d);
                q = (d != 0.0f) ? q : 0.0f;
                acc_s = fmaf(q, q, acc_s);
            };
            const float4 dd[4] = {d0, d1, d2, d3};
            #pragma unroll
            for (int k = 0; k < ROWS_PER_CTA; k++) {
                safe(dd[k].x, x4.x, y4.x, nx[k].f.x, ny[k].f.x);
                safe(dd[k].y, x4.y, y4.y, nx[k].f.x, ny[k].f.x);
                safe(dd[k].z, x4.z, y4.z, nx[k].f.x, ny[k].f.x);
                safe(dd[k].w, x4.w, y4.w, nx[k].f.x, ny[k].f.x);
            }
        }
    }

    float acc = (acc01.f.x + acc01.f.y) + (acc23.f.x + acc23.f.y) + acc_s;

    // intra-CTA deterministic reduction
    #pragma unroll
    for (int o = 16; o > 0; o >>= 1)
        acc += __shfl_down_sync(0xffffffffu, acc, o);

    __shared__ float warpsum[THREADS / 32];
    const int lane = tid & 31;
    const int wid  = tid >> 5;
    if (lane == 0) warpsum[wid] = acc;
    __syncthreads();

    __shared__ bool is_last;
    if (tid == 0) {
        float v = 0.0f;
        #pragma unroll
        for (int w = 0; w < THREADS / 32; w++) v += warpsum[w];
        g_partials[blockIdx.x] = v;
        __threadfence();
        unsigned int prev = atomicAdd(&g_count, 1u);
        is_last = (prev == NUM_BLOCKS - 1);
    }
    __syncthreads();

    if (is_last) {
        __shared__ double s[THREADS];
        double t = 0.0;
        const float4* p4 = reinterpret_cast<const float4*>(g_partials);
        #pragma unroll
        for (int k = 0; k < NUM_BLOCKS / THREADS / 4; k++) {
            float4 v = p4[tid * (NUM_BLOCKS / THREADS / 4) + k];
            t += (double)v.x + (double)v.y + (double)v.z + (double)v.w;
        }
        s[tid] = t;
        __syncthreads();
        #pragma unroll
        for (int o = THREADS / 2; o > 0; o >>= 1) {
            if (tid < o) s[tid] += s[tid + o];
            __syncthreads();
        }
        if (tid == 0) {
            out[0] = (float)s[0];
            g_count = 0;                 // reset for next graph replay
            g_flag  = 0;
        }
    }
}

extern "C" void kernel_launch(void* const* d_in, const int* in_sizes, int n_in,
                              void* d_out, int out_size) {
    const float* a = (const float*)d_in[0];
    const float* b = (const float*)d_in[1];
    const float2* pos2;
    const float*  dist;
    if (in_sizes[0] < in_sizes[1]) { pos2 = (const float2*)a; dist = b; }
    else                           { pos2 = (const float2*)b; dist = a; }

    stress_kernel<<<NUM_BLOCKS, THREADS>>>(pos2, dist, (float*)d_out);
}

// round 17
// speedup vs baseline: 1.0391x; 1.0391x over previous
#include <cuda_runtime.h>

#define N 8192
#define THREADS 256
#define ROWS_PER_CTA 4
#define COL_HALF 4096
#define NUM_BLOCKS ((N / ROWS_PER_CTA) * 2)        // 4096: 4 rows x half width
#define COLS_PER_THREAD 4
#define ITERS (COL_HALF / (THREADS * COLS_PER_THREAD))   // 4

typedef unsigned long long ull;
union f2u { float2 f; ull u; };

__device__ float        g_partials[NUM_BLOCKS];
__device__ unsigned int g_count = 0;

__device__ __forceinline__ ull f2add(ull a, ull b) {
    ull c; asm("add.rn.f32x2 %0, %1, %2;" : "=l"(c) : "l"(a), "l"(b)); return c;
}
__device__ __forceinline__ ull f2mul(ull a, ull b) {
    ull c; asm("mul.rn.f32x2 %0, %1, %2;" : "=l"(c) : "l"(a), "l"(b)); return c;
}
__device__ __forceinline__ ull f2fma(ull a, ull b, ull c) {
    ull d; asm("fma.rn.f32x2 %0, %1, %2, %3;" : "=l"(d) : "l"(a), "l"(b), "l"(c)); return d;
}
__device__ __forceinline__ float fsqrt_a(float x) {
    float r; asm("sqrt.approx.f32 %0, %1;" : "=f"(r) : "f"(x)); return r;
}
__device__ __forceinline__ float frcp_a(float x) {
    float r; asm("rcp.approx.f32 %0, %1;" : "=f"(r) : "f"(x)); return r;
}

__global__ __launch_bounds__(THREADS, 5)
void stress_kernel(const float2* __restrict__ pos2,
                   const float*  __restrict__ dist,
                   float* __restrict__ out) {
    const int tid  = threadIdx.x;
    const int row0 = ((int)blockIdx.x >> 1) * ROWS_PER_CTA;
    const int col0 = ((int)blockIdx.x & 1) * COL_HALF;

    const float4* pos4 = reinterpret_cast<const float4*>(pos2);

    f2u nx[ROWS_PER_CTA], ny[ROWS_PER_CTA];
    #pragma unroll
    for (int k = 0; k < ROWS_PER_CTA; k++) {
        float2 p = __ldg(&pos2[row0 + k]);
        nx[k].f.x = -p.x; nx[k].f.y = -p.x;
        ny[k].f.x = -p.y; ny[k].f.y = -p.y;
    }

    const float* dr0 = dist + (size_t)row0 * N + col0;
    const float* dr1 = dr0 + N;
    const float* dr2 = dr1 + N;
    const float* dr3 = dr2 + N;

    f2u acc01, acc23;
    acc01.f.x = 0.f; acc01.f.y = 0.f;
    acc23.f.x = 0.f; acc23.f.y = 0.f;
    float acc_s = 0.f;

    f2u NEG1; NEG1.f.x = -1.f; NEG1.f.y = -1.f;

    for (int it = 0; it < ITERS; it++) {
        const int c = (it * THREADS + tid) * COLS_PER_THREAD;
        const int j = col0 + c;

        // AoS pos pairs: p01 = {x_j, y_j, x_j+1, y_j+1}, p23 = cols j+2, j+3
        float4 p01 = __ldg(&pos4[j >> 1]);
        float4 p23 = __ldg(&pos4[(j >> 1) + 1]);

        float4 d0 = __ldcs(reinterpret_cast<const float4*>(dr0 + c));
        float4 d1 = __ldcs(reinterpret_cast<const float4*>(dr1 + c));
        float4 d2 = __ldcs(reinterpret_cast<const float4*>(dr2 + c));
        float4 d3 = __ldcs(reinterpret_cast<const float4*>(dr3 + c));

        // Montgomery prefix products (reused in the fast path) double as the
        // zero detector: q0123 == 0  <=>  some d in the group == 0.
        // (FTZ underflow of a product of 4 uniforms is ~impossible; if it
        //  ever fires it just routes to the exact fallback -> still correct.)
        float a01_0 = d0.x * d0.y, a012_0 = a01_0 * d0.z, a0123_0 = a012_0 * d0.w;
        float a01_1 = d1.x * d1.y, a012_1 = a01_1 * d1.z, a0123_1 = a012_1 * d1.w;
        float a01_2 = d2.x * d2.y, a012_2 = a01_2 * d2.z, a0123_2 = a012_2 * d2.w;
        float a01_3 = d3.x * d3.y, a012_3 = a01_3 * d3.z, a0123_3 = a012_3 * d3.w;
        float prod  = (a0123_0 * a0123_1) * (a0123_2 * a0123_3);

        if (prod != 0.0f) {
            // packed column pairs straight from AoS components
            f2u xa, xb, ya, yb;
            xa.f.x = p01.x; xa.f.y = p01.z;  ya.f.x = p01.y; ya.f.y = p01.w;
            xb.f.x = p23.x; xb.f.y = p23.z;  yb.f.x = p23.y; yb.f.y = p23.w;

            auto grp = [&](const float4& d, float q01, float q012, float q0123,
                           ull nxp, ull nyp) {
                // Montgomery batched reciprocal: 1 MUFU.RCP / 4 elems
                float R  = frcp_a(q0123);
                float i3 = q012 * R;  float R3 = R  * d.w;
                float i2 = q01  * R3; float R2 = R3 * d.z;
                float i1 = d.x  * R2; float i0 = d.y * R2;
                f2u iv01; iv01.f.x = i0; iv01.f.y = i1;
                f2u iv23; iv23.f.x = i2; iv23.f.y = i3;

                ull dxa = f2add(xa.u, nxp);
                ull dya = f2add(ya.u, nyp);
                ull sqa = f2fma(dya, dya, f2mul(dxa, dxa));
                f2u sa; sa.u = sqa;
                f2u pa; pa.f.x = fsqrt_a(sa.f.x); pa.f.y = fsqrt_a(sa.f.y);
                ull qa = f2fma(pa.u, iv01.u, NEG1.u);     // pred/d - 1
                acc01.u = f2fma(qa, qa, acc01.u);

                ull dxb = f2add(xb.u, nxp);
                ull dyb = f2add(yb.u, nyp);
                ull sqb = f2fma(dyb, dyb, f2mul(dxb, dxb));
                f2u sb; sb.u = sqb;
                f2u pb; pb.f.x = fsqrt_a(sb.f.x); pb.f.y = fsqrt_a(sb.f.y);
                ull qb = f2fma(pb.u, iv23.u, NEG1.u);
                acc23.u = f2fma(qb, qb, acc23.u);
            };

            grp(d0, a01_0, a012_0, a0123_0, nx[0].u, ny[0].u);
            grp(d1, a01_1, a012_1, a0123_1, nx[1].u, ny[1].u);
            grp(d2, a01_2, a012_2, a0123_2, nx[2].u, ny[2].u);
            grp(d3, a01_3, a012_3, a0123_3, nx[3].u, ny[3].u);
        } else {
            // exact scalar fallback (rare: group contains a zero distance)
            auto safe = [&](float d, float xj, float yj, float px, float py) {
                float dx = xj + px, dy = yj + py;
                float sq = fmaf(dy, dy, dx * dx);
                float pr = fsqrt_a(sq);
                float q  = (pr - d) * frcp_a(d);
                q = (d != 0.0f) ? q : 0.0f;
                acc_s = fmaf(q, q, acc_s);
            };
            const float4 dd[4] = {d0, d1, d2, d3};
            #pragma unroll
            for (int k = 0; k < ROWS_PER_CTA; k++) {
                safe(dd[k].x, p01.x, p01.y, nx[k].f.x, ny[k].f.x);
                safe(dd[k].y, p01.z, p01.w, nx[k].f.x, ny[k].f.x);
                safe(dd[k].z, p23.x, p23.y, nx[k].f.x, ny[k].f.x);
                safe(dd[k].w, p23.z, p23.w, nx[k].f.x, ny[k].f.x);
            }
        }
    }

    float acc = (acc01.f.x + acc01.f.y) + (acc23.f.x + acc23.f.y) + acc_s;

    // intra-CTA deterministic reduction
    #pragma unroll
    for (int o = 16; o > 0; o >>= 1)
        acc += __shfl_down_sync(0xffffffffu, acc, o);

    __shared__ float warpsum[THREADS / 32];
    const int lane = tid & 31;
    const int wid  = tid >> 5;
    if (lane == 0) warpsum[wid] = acc;
    __syncthreads();

    __shared__ bool is_last;
    if (tid == 0) {
        float v = 0.0f;
        #pragma unroll
        for (int w = 0; w < THREADS / 32; w++) v += warpsum[w];
        g_partials[blockIdx.x] = v;
        __threadfence();
        unsigned int prev = atomicAdd(&g_count, 1u);
        is_last = (prev == NUM_BLOCKS - 1);
    }
    __syncthreads();

    if (is_last) {
        __shared__ double s[THREADS];
        double t = 0.0;
        const float4* p4 = reinterpret_cast<const float4*>(g_partials);
        #pragma unroll
        for (int k = 0; k < NUM_BLOCKS / THREADS / 4; k++) {
            float4 v = p4[tid * (NUM_BLOCKS / THREADS / 4) + k];
            t += (double)v.x + (double)v.y + (double)v.z + (double)v.w;
        }
        s[tid] = t;
        __syncthreads();
        #pragma unroll
        for (int o = THREADS / 2; o > 0; o >>= 1) {
            if (tid < o) s[tid] += s[tid + o];
            __syncthreads();
        }
        if (tid == 0) {
            out[0] = (float)s[0];
            g_count = 0;                 // reset for next graph replay
        }
    }
}

extern "C" void kernel_launch(void* const* d_in, const int* in_sizes, int n_in,
                              void* d_out, int out_size) {
    const float* a = (const float*)d_in[0];
    const float* b = (const float*)d_in[1];
    const float2* pos2;
    const float*  dist;
    if (in_sizes[0] < in_sizes[1]) { pos2 = (const float2*)a; dist = b; }
    else                           { pos2 = (const float2*)b; dist = a; }

    stress_kernel<<<NUM_BLOCKS, THREADS>>>(pos2, dist, (float*)d_out);
}